// round 3
// baseline (speedup 1.0000x reference)
#include <cuda_runtime.h>
#include <cuda_bf16.h>
#include <cstdint>

#define BATCH 64
#define SEQ_T 1024
#define HID   1024
#define NTAG  64
#define BT    (BATCH * SEQ_T)          // 65536 rows
#define BTN   (BT * NTAG)              // 4194304 emission elems

// ---------------------------------------------------------------------------
// Kernel 1: emission GEMM  C[m][n] = sum_h A[m][h] * W[n][h] + b[n]
// (unchanged from R1 — measured at the fp32 FFMA roofline, ~247us)
// ---------------------------------------------------------------------------
#define TM 128
#define TK 64

__global__ __launch_bounds__(256) void emission_kernel(
    const float* __restrict__ A,
    const float* __restrict__ W,
    const float* __restrict__ bias,
    float* __restrict__ C)
{
    __shared__ float sA[TM][TK + 1];
    __shared__ float sW[NTAG][TK + 1];

    const int m0  = blockIdx.x * TM;
    const int tid = threadIdx.x;
    const int tx  = tid & 15;   // n-group (4 cols each)
    const int ty  = tid >> 4;   // m-group (8 rows each)

    float acc[8][4];
#pragma unroll
    for (int r = 0; r < 8; r++)
#pragma unroll
        for (int c = 0; c < 4; c++) acc[r][c] = 0.0f;

    float bc[4];
#pragma unroll
    for (int c = 0; c < 4; c++) bc[c] = bias[tx * 4 + c];

    const int lrow = tid >> 4;
    const int lc4  = (tid & 15) * 4;

    for (int k0 = 0; k0 < HID; k0 += TK) {
#pragma unroll
        for (int p = 0; p < 8; p++) {
            const int row = p * 16 + lrow;
            float4 v = *(const float4*)&A[(size_t)(m0 + row) * HID + k0 + lc4];
            sA[row][lc4 + 0] = v.x; sA[row][lc4 + 1] = v.y;
            sA[row][lc4 + 2] = v.z; sA[row][lc4 + 3] = v.w;
        }
#pragma unroll
        for (int p = 0; p < 4; p++) {
            const int row = p * 16 + lrow;
            float4 v = *(const float4*)&W[(size_t)row * HID + k0 + lc4];
            sW[row][lc4 + 0] = v.x; sW[row][lc4 + 1] = v.y;
            sW[row][lc4 + 2] = v.z; sW[row][lc4 + 3] = v.w;
        }
        __syncthreads();

#pragma unroll 16
        for (int kk = 0; kk < TK; kk++) {
            float a[8], w[4];
#pragma unroll
            for (int r = 0; r < 8; r++) a[r] = sA[ty * 8 + r][kk];
#pragma unroll
            for (int c = 0; c < 4; c++) w[c] = sW[tx * 4 + c][kk];
#pragma unroll
            for (int r = 0; r < 8; r++)
#pragma unroll
                for (int c = 0; c < 4; c++) acc[r][c] += a[r] * w[c];
        }
        __syncthreads();
    }

#pragma unroll
    for (int r = 0; r < 8; r++) {
        const size_t base = (size_t)(m0 + ty * 8 + r) * NTAG + tx * 4;
#pragma unroll
        for (int c = 0; c < 4; c++) C[base + c] = acc[r][c] + bc[c];
    }
}

// ---------------------------------------------------------------------------
// Kernel 2: Viterbi. One CTA per batch, 256 threads, j = tid>>2, sub = tid&3.
// R2 change: serial predicated argmax chain (16 x ~17cyc FSETP dependency)
// replaced by a parallel (value,index) merge tree: 15 nodes of
// {FMNMX, FSETP.GE, SEL}, depth 4. Tie semantics = first occurrence (lower i)
// exactly as jnp.argmax: left subtree always holds smaller indices, ">=" keeps
// left; cross-sub shfl reduce prefers smaller index on exact tie.
// ---------------------------------------------------------------------------
__global__ __launch_bounds__(256) void viterbi_kernel(
    const float* __restrict__ emission,     // [B, T, N]
    const float* __restrict__ start_trans,  // [N]
    const float* __restrict__ end_trans,    // [N]
    const float* __restrict__ trans,        // [N, N] row-major
    float* __restrict__ tags_out,           // [B, T] as float
    int write_tags)
{
    extern __shared__ unsigned char dsm[];
    unsigned char* hist = dsm;                          // [T][N] bytes
    float* score = (float*)(dsm + SEQ_T * NTAG);        // [2][N]

    const int b   = blockIdx.x;
    const int tid = threadIdx.x;
    const int j   = tid >> 2;
    const int sub = tid & 3;
    const int i0  = sub * 16;

    // trans column j for my 16 prev-tags, in registers
    float treg[16];
#pragma unroll
    for (int k = 0; k < 16; k++) treg[k] = trans[(i0 + k) * NTAG + j];

    const float* eb = emission + (size_t)b * SEQ_T * NTAG;

    if (sub == 0) score[j] = start_trans[j] + eb[j];
    __syncthreads();

    float e_next = eb[NTAG + j];   // emission for t=1
    int cur = 0;

    for (int t = 1; t < SEQ_T; t++) {
        const float e_cur = e_next;
        if (t + 1 < SEQ_T) e_next = eb[(size_t)(t + 1) * NTAG + j];

        // 16 candidates, loaded as 4 float4s
        const float4* sp = (const float4*)(score + cur * NTAG + i0);
        float c[16];
#pragma unroll
        for (int q = 0; q < 4; q++) {
            float4 s4 = sp[q];
            c[q * 4 + 0] = s4.x + treg[q * 4 + 0];
            c[q * 4 + 1] = s4.y + treg[q * 4 + 1];
            c[q * 4 + 2] = s4.z + treg[q * 4 + 2];
            c[q * 4 + 3] = s4.w + treg[q * 4 + 3];
        }

        // parallel (value, index) merge tree, first-occurrence ties
        float v8[8]; int x8[8];
#pragma unroll
        for (int k = 0; k < 8; k++) {
            bool p = c[2 * k] >= c[2 * k + 1];
            v8[k] = fmaxf(c[2 * k], c[2 * k + 1]);
            x8[k] = p ? (2 * k) : (2 * k + 1);
        }
        float v4[4]; int x4[4];
#pragma unroll
        for (int k = 0; k < 4; k++) {
            bool p = v8[2 * k] >= v8[2 * k + 1];
            v4[k] = fmaxf(v8[2 * k], v8[2 * k + 1]);
            x4[k] = p ? x8[2 * k] : x8[2 * k + 1];
        }
        float v2[2]; int x2[2];
#pragma unroll
        for (int k = 0; k < 2; k++) {
            bool p = v4[2 * k] >= v4[2 * k + 1];
            v2[k] = fmaxf(v4[2 * k], v4[2 * k + 1]);
            x2[k] = p ? x4[2 * k] : x4[2 * k + 1];
        }
        bool p0 = v2[0] >= v2[1];
        float best = fmaxf(v2[0], v2[1]);
        int   bidx = (p0 ? x2[0] : x2[1]) + i0;

        // combine the 4 sub-partials (lanes differ only in low-2 bits)
#pragma unroll
        for (int off = 1; off <= 2; off <<= 1) {
            float ov = __shfl_xor_sync(0xffffffffu, best, off);
            int   oi = __shfl_xor_sync(0xffffffffu, bidx, off);
            bool take = (ov > best) || (ov == best && oi < bidx);
            best = fmaxf(best, ov);
            bidx = take ? oi : bidx;
        }

        if (sub == 0) {
            score[(cur ^ 1) * NTAG + j] = best + e_cur;
            hist[t * NTAG + j] = (unsigned char)bidx;
        }
        __syncthreads();
        cur ^= 1;
    }

    if (sub == 0) score[cur * NTAG + j] += end_trans[j];
    __syncthreads();

    if (tid == 0 && write_tags) {
        float bestv = score[cur * NTAG];
        int bt = 0;
        for (int jj = 1; jj < NTAG; jj++) {
            float v = score[cur * NTAG + jj];
            if (v > bestv) { bestv = v; bt = jj; }
        }
        float* to = tags_out + (size_t)b * SEQ_T;
        int tag = bt;
        to[SEQ_T - 1] = (float)tag;
        for (int t = SEQ_T - 1; t >= 1; t--) {
            tag = hist[t * NTAG + tag];
            to[t - 1] = (float)tag;
        }
    }
}

// ---------------------------------------------------------------------------
// Host launcher
// ---------------------------------------------------------------------------
extern "C" void kernel_launch(void* const* d_in, const int* in_sizes, int n_in,
                              void* d_out, int out_size)
{
    const float* text        = (const float*)d_in[0];
    const float* W_em        = (const float*)d_in[2];
    const float* b_em        = (const float*)d_in[3];
    const float* start_trans = (const float*)d_in[4];
    const float* end_trans   = (const float*)d_in[5];
    const float* trans       = (const float*)d_in[6];
    float* out = (float*)d_out;

    emission_kernel<<<BT / TM, 256>>>(text, W_em, b_em, out);

    const int smem_bytes = SEQ_T * NTAG + 2 * NTAG * (int)sizeof(float);
    cudaFuncSetAttribute(viterbi_kernel,
                         cudaFuncAttributeMaxDynamicSharedMemorySize, smem_bytes);
    const int write_tags = (out_size >= BTN + BT) ? 1 : 0;
    viterbi_kernel<<<BATCH, 256, smem_bytes>>>(
        out, start_trans, end_trans, trans, out + BTN, write_tags);
}

// round 4
// speedup vs baseline: 1.2940x; 1.2940x over previous
#include <cuda_runtime.h>
#include <cuda_bf16.h>
#include <cstdint>

#define BATCH 64
#define SEQ_T 1024
#define HID   1024
#define NTAG  64
#define BT    (BATCH * SEQ_T)          // 65536 rows
#define BTN   (BT * NTAG)              // 4194304 emission elems

// ---------------------------------------------------------------------------
// Kernel 1: emission GEMM with packed f32x2 FMA (FFMA2).
// C[m][n] = sum_h A[m][h] * W[n][h] + b[n]
// Tile: 128 M x 64 N, K-slab 64. 128 threads, 8x8 outputs/thread.
// smem tiles stored k-major (transposed) so A row-pairs load as ulonglong2.
// ---------------------------------------------------------------------------
#define TM 128
#define TK 64

__global__ __launch_bounds__(128) void emission_kernel(
    const float* __restrict__ A,
    const float* __restrict__ W,
    const float* __restrict__ bias,
    float* __restrict__ C)
{
    __shared__ float sA[TK][TM];      // k-major: sA[k][m]
    __shared__ float sW[TK][NTAG];    // k-major: sW[k][n]

    const int m0  = blockIdx.x * TM;
    const int tid = threadIdx.x;
    const int tx  = tid & 7;          // col group: 8 cols
    const int ty  = tid >> 3;         // row group: 8 rows

    // accumulators: 4 row-pairs x 8 cols, packed f32x2
    unsigned long long acc[4][8];
#pragma unroll
    for (int r = 0; r < 4; r++)
#pragma unroll
        for (int c = 0; c < 8; c++) acc[r][c] = 0ull;

    for (int k0 = 0; k0 < HID; k0 += TK) {
        // Load A slab: thread t owns global row m0+t, 16 float4 across k
        {
            const float* arow = &A[(size_t)(m0 + tid) * HID + k0];
#pragma unroll
            for (int q = 0; q < 16; q++) {
                float4 v = *(const float4*)(arow + q * 4);
                sA[q * 4 + 0][tid] = v.x;
                sA[q * 4 + 1][tid] = v.y;
                sA[q * 4 + 2][tid] = v.z;
                sA[q * 4 + 3][tid] = v.w;
            }
        }
        // Load W slab: thread t owns W row (t&63), half the k-columns each
        {
            const int wr = tid & 63;
            const int qh = (tid >> 6) * 8;   // 0 or 8
            const float* wrow = &W[(size_t)wr * HID + k0];
#pragma unroll
            for (int q = 0; q < 8; q++) {
                float4 v = *(const float4*)(wrow + (qh + q) * 4);
                sW[(qh + q) * 4 + 0][wr] = v.x;
                sW[(qh + q) * 4 + 1][wr] = v.y;
                sW[(qh + q) * 4 + 2][wr] = v.z;
                sW[(qh + q) * 4 + 3][wr] = v.w;
            }
        }
        __syncthreads();

#pragma unroll 8
        for (int kk = 0; kk < TK; kk++) {
            // 8 A values = 4 packed pairs (free pairing via 128-bit loads)
            ulonglong2 a01 = *(const ulonglong2*)&sA[kk][ty * 8];
            ulonglong2 a23 = *(const ulonglong2*)&sA[kk][ty * 8 + 4];
            unsigned long long ap[4] = {a01.x, a01.y, a23.x, a23.y};

            float4 wA = *(const float4*)&sW[kk][tx * 8];
            float4 wB = *(const float4*)&sW[kk][tx * 8 + 4];
            float wv[8] = {wA.x, wA.y, wA.z, wA.w, wB.x, wB.y, wB.z, wB.w};

            unsigned long long wd[8];
#pragma unroll
            for (int c = 0; c < 8; c++)
                asm("mov.b64 %0, {%1, %1};" : "=l"(wd[c]) : "r"(__float_as_uint(wv[c])));

#pragma unroll
            for (int r = 0; r < 4; r++)
#pragma unroll
                for (int c = 0; c < 8; c++)
                    asm("fma.rn.f32x2 %0, %1, %2, %0;"
                        : "+l"(acc[r][c]) : "l"(ap[r]), "l"(wd[c]));
        }
        __syncthreads();
    }

    // epilogue: unpack, add bias, store
    float bc[8];
#pragma unroll
    for (int c = 0; c < 8; c++) bc[c] = bias[tx * 8 + c];

#pragma unroll
    for (int r = 0; r < 4; r++) {
        unsigned int lo[8], hi[8];
#pragma unroll
        for (int c = 0; c < 8; c++)
            asm("mov.b64 {%0, %1}, %2;" : "=r"(lo[c]), "=r"(hi[c]) : "l"(acc[r][c]));
        const size_t base0 = (size_t)(m0 + ty * 8 + 2 * r)     * NTAG + tx * 8;
        const size_t base1 = (size_t)(m0 + ty * 8 + 2 * r + 1) * NTAG + tx * 8;
        float4 o0a, o0b, o1a, o1b;
        o0a.x = __uint_as_float(lo[0]) + bc[0]; o0a.y = __uint_as_float(lo[1]) + bc[1];
        o0a.z = __uint_as_float(lo[2]) + bc[2]; o0a.w = __uint_as_float(lo[3]) + bc[3];
        o0b.x = __uint_as_float(lo[4]) + bc[4]; o0b.y = __uint_as_float(lo[5]) + bc[5];
        o0b.z = __uint_as_float(lo[6]) + bc[6]; o0b.w = __uint_as_float(lo[7]) + bc[7];
        o1a.x = __uint_as_float(hi[0]) + bc[0]; o1a.y = __uint_as_float(hi[1]) + bc[1];
        o1a.z = __uint_as_float(hi[2]) + bc[2]; o1a.w = __uint_as_float(hi[3]) + bc[3];
        o1b.x = __uint_as_float(hi[4]) + bc[4]; o1b.y = __uint_as_float(hi[5]) + bc[5];
        o1b.z = __uint_as_float(hi[6]) + bc[6]; o1b.w = __uint_as_float(hi[7]) + bc[7];
        *(float4*)&C[base0]     = o0a;  *(float4*)&C[base0 + 4] = o0b;
        *(float4*)&C[base1]     = o1a;  *(float4*)&C[base1 + 4] = o1b;
    }
}

// ---------------------------------------------------------------------------
// Kernel 2: Viterbi. 64 CTAs (one per batch) x 64 threads (2 warps).
// Lane j owns tag column j: 64 in-register candidates per step, grouped
// max (4-wide) + exact first-occurrence argmax fixup. No shuffles; one
// 2-warp barrier per step. History in shared memory for fast backtrack.
// ---------------------------------------------------------------------------
__global__ __launch_bounds__(64) void viterbi_kernel(
    const float* __restrict__ emission,     // [B, T, N]
    const float* __restrict__ start_trans,  // [N]
    const float* __restrict__ end_trans,    // [N]
    const float* __restrict__ trans,        // [N, N] row-major
    float* __restrict__ tags_out,           // [B, T] as float
    int write_tags)
{
    extern __shared__ unsigned char dsm[];
    float* score  = (float*)dsm;                            // [2][NTAG]
    float* transT = (float*)(dsm + 2 * NTAG * 4);           // [NTAG][65]
    unsigned char* hist = dsm + 2 * NTAG * 4 + NTAG * 65 * 4; // [T][NTAG]

    const int b = blockIdx.x;
    const int j = threadIdx.x;   // 0..63

    // trans column j -> registers (coalesced loads) + smem copy for fixup
    float tr[64];
#pragma unroll
    for (int i = 0; i < 64; i++) {
        tr[i] = trans[i * NTAG + j];
        transT[j * 65 + i] = tr[i];
    }

    const float* eb = emission + (size_t)b * SEQ_T * NTAG;

    score[j] = start_trans[j] + eb[j];
    __syncthreads();

    const float NEG_INF = __int_as_float(0xff800000);
    float e_next = eb[NTAG + j];
    int cur = 0;

    for (int t = 1; t < SEQ_T; t++) {
        const float e_cur = e_next;
        if (t + 1 < SEQ_T) e_next = eb[(size_t)(t + 1) * NTAG + j];

        const float4* sp = (const float4*)(score + cur * NTAG);
        float best = NEG_INF;
        int gbase = 0;
#pragma unroll
        for (int g = 0; g < 16; g++) {
            float4 s4 = sp[g];
            float c0 = s4.x + tr[4 * g + 0];
            float c1 = s4.y + tr[4 * g + 1];
            float c2 = s4.z + tr[4 * g + 2];
            float c3 = s4.w + tr[4 * g + 3];
            float gm = fmaxf(fmaxf(c0, c1), fmaxf(c2, c3));
            bool p = gm > best;              // strict: keep earliest group
            best  = fmaxf(best, gm);
            gbase = p ? 4 * g : gbase;
        }
        // exact first-occurrence index inside winning group
        const float* sc = score + cur * NTAG;
        const float* tj = transT + j * 65;
        float f0 = sc[gbase + 0] + tj[gbase + 0];
        float f1 = sc[gbase + 1] + tj[gbase + 1];
        float f2 = sc[gbase + 2] + tj[gbase + 2];
        int idx = gbase + 3;
        if (f2 == best) idx = gbase + 2;
        if (f1 == best) idx = gbase + 1;
        if (f0 == best) idx = gbase + 0;

        score[(cur ^ 1) * NTAG + j] = best + e_cur;
        hist[t * NTAG + j] = (unsigned char)idx;
        __syncthreads();
        cur ^= 1;
    }

    score[cur * NTAG + j] += end_trans[j];
    __syncthreads();

    if (j == 0 && write_tags) {
        float bestv = score[cur * NTAG];
        int bt = 0;
        for (int jj = 1; jj < NTAG; jj++) {
            float v = score[cur * NTAG + jj];
            if (v > bestv) { bestv = v; bt = jj; }
        }
        float* to = tags_out + (size_t)b * SEQ_T;
        int tag = bt;
        to[SEQ_T - 1] = (float)tag;
        for (int t = SEQ_T - 1; t >= 1; t--) {
            tag = hist[t * NTAG + tag];
            to[t - 1] = (float)tag;
        }
    }
}

// ---------------------------------------------------------------------------
// Host launcher
// ---------------------------------------------------------------------------
extern "C" void kernel_launch(void* const* d_in, const int* in_sizes, int n_in,
                              void* d_out, int out_size)
{
    const float* text        = (const float*)d_in[0];
    const float* W_em        = (const float*)d_in[2];
    const float* b_em        = (const float*)d_in[3];
    const float* start_trans = (const float*)d_in[4];
    const float* end_trans   = (const float*)d_in[5];
    const float* trans       = (const float*)d_in[6];
    float* out = (float*)d_out;

    emission_kernel<<<BT / TM, 128>>>(text, W_em, b_em, out);

    const int smem_bytes = 2 * NTAG * 4 + NTAG * 65 * 4 + SEQ_T * NTAG;
    cudaFuncSetAttribute(viterbi_kernel,
                         cudaFuncAttributeMaxDynamicSharedMemorySize, smem_bytes);
    const int write_tags = (out_size >= BTN + BT) ? 1 : 0;
    viterbi_kernel<<<BATCH, 64, smem_bytes>>>(
        out, start_trans, end_trans, trans, out + BTN, write_tags);
}

// round 5
// speedup vs baseline: 1.5279x; 1.1808x over previous
#include <cuda_runtime.h>
#include <cuda_bf16.h>
#include <cstdint>

#define BATCH 64
#define SEQ_T 1024
#define HID   1024
#define NTAG  64
#define BT    (BATCH * SEQ_T)          // 65536 rows
#define BTN   (BT * NTAG)              // 4194304 emission elems

// ---------------------------------------------------------------------------
// Kernel 1: emission GEMM with packed f32x2 FMA (FFMA2). (unchanged R3 —
// measured ~144us, near the 2x-FFMA2 floor)
// ---------------------------------------------------------------------------
#define TM 128
#define TK 64

__global__ __launch_bounds__(128) void emission_kernel(
    const float* __restrict__ A,
    const float* __restrict__ W,
    const float* __restrict__ bias,
    float* __restrict__ C)
{
    __shared__ float sA[TK][TM];      // k-major: sA[k][m]
    __shared__ float sW[TK][NTAG];    // k-major: sW[k][n]

    const int m0  = blockIdx.x * TM;
    const int tid = threadIdx.x;
    const int tx  = tid & 7;
    const int ty  = tid >> 3;

    unsigned long long acc[4][8];
#pragma unroll
    for (int r = 0; r < 4; r++)
#pragma unroll
        for (int c = 0; c < 8; c++) acc[r][c] = 0ull;

    for (int k0 = 0; k0 < HID; k0 += TK) {
        {
            const float* arow = &A[(size_t)(m0 + tid) * HID + k0];
#pragma unroll
            for (int q = 0; q < 16; q++) {
                float4 v = *(const float4*)(arow + q * 4);
                sA[q * 4 + 0][tid] = v.x;
                sA[q * 4 + 1][tid] = v.y;
                sA[q * 4 + 2][tid] = v.z;
                sA[q * 4 + 3][tid] = v.w;
            }
        }
        {
            const int wr = tid & 63;
            const int qh = (tid >> 6) * 8;
            const float* wrow = &W[(size_t)wr * HID + k0];
#pragma unroll
            for (int q = 0; q < 8; q++) {
                float4 v = *(const float4*)(wrow + (qh + q) * 4);
                sW[(qh + q) * 4 + 0][wr] = v.x;
                sW[(qh + q) * 4 + 1][wr] = v.y;
                sW[(qh + q) * 4 + 2][wr] = v.z;
                sW[(qh + q) * 4 + 3][wr] = v.w;
            }
        }
        __syncthreads();

#pragma unroll 8
        for (int kk = 0; kk < TK; kk++) {
            ulonglong2 a01 = *(const ulonglong2*)&sA[kk][ty * 8];
            ulonglong2 a23 = *(const ulonglong2*)&sA[kk][ty * 8 + 4];
            unsigned long long ap[4] = {a01.x, a01.y, a23.x, a23.y};

            float4 wA = *(const float4*)&sW[kk][tx * 8];
            float4 wB = *(const float4*)&sW[kk][tx * 8 + 4];
            float wv[8] = {wA.x, wA.y, wA.z, wA.w, wB.x, wB.y, wB.z, wB.w};

            unsigned long long wd[8];
#pragma unroll
            for (int c = 0; c < 8; c++)
                asm("mov.b64 %0, {%1, %1};" : "=l"(wd[c]) : "r"(__float_as_uint(wv[c])));

#pragma unroll
            for (int r = 0; r < 4; r++)
#pragma unroll
                for (int c = 0; c < 8; c++)
                    asm("fma.rn.f32x2 %0, %1, %2, %0;"
                        : "+l"(acc[r][c]) : "l"(ap[r]), "l"(wd[c]));
        }
        __syncthreads();
    }

    float bc[8];
#pragma unroll
    for (int c = 0; c < 8; c++) bc[c] = bias[tx * 8 + c];

#pragma unroll
    for (int r = 0; r < 4; r++) {
        unsigned int lo[8], hi[8];
#pragma unroll
        for (int c = 0; c < 8; c++)
            asm("mov.b64 {%0, %1}, %2;" : "=r"(lo[c]), "=r"(hi[c]) : "l"(acc[r][c]));
        const size_t base0 = (size_t)(m0 + ty * 8 + 2 * r)     * NTAG + tx * 8;
        const size_t base1 = (size_t)(m0 + ty * 8 + 2 * r + 1) * NTAG + tx * 8;
        float4 o0a, o0b, o1a, o1b;
        o0a.x = __uint_as_float(lo[0]) + bc[0]; o0a.y = __uint_as_float(lo[1]) + bc[1];
        o0a.z = __uint_as_float(lo[2]) + bc[2]; o0a.w = __uint_as_float(lo[3]) + bc[3];
        o0b.x = __uint_as_float(lo[4]) + bc[4]; o0b.y = __uint_as_float(lo[5]) + bc[5];
        o0b.z = __uint_as_float(lo[6]) + bc[6]; o0b.w = __uint_as_float(lo[7]) + bc[7];
        o1a.x = __uint_as_float(hi[0]) + bc[0]; o1a.y = __uint_as_float(hi[1]) + bc[1];
        o1a.z = __uint_as_float(hi[2]) + bc[2]; o1a.w = __uint_as_float(hi[3]) + bc[3];
        o1b.x = __uint_as_float(hi[4]) + bc[4]; o1b.y = __uint_as_float(hi[5]) + bc[5];
        o1b.z = __uint_as_float(hi[6]) + bc[6]; o1b.w = __uint_as_float(hi[7]) + bc[7];
        *(float4*)&C[base0]     = o0a;  *(float4*)&C[base0 + 4] = o0b;
        *(float4*)&C[base1]     = o1a;  *(float4*)&C[base1 + 4] = o1b;
    }
}

// ---------------------------------------------------------------------------
// Kernel 2: Viterbi. 64 CTAs x 64 threads. R4: t-loop unrolled x4 with a
// 4-deep emission register pipeline (MLP=4 LDG, consumed ~4 steps later);
// (value,group) keep-left merge tree (depth 4); score STS issued BEFORE the
// index fixup so the inter-step critical path is LDS->FADD->tree->STS->bar.
// ---------------------------------------------------------------------------
__device__ __forceinline__ void vstep(
    const float* __restrict__ sc_in, float* __restrict__ sc_out,
    const float* tr,            // reg array (constant-indexed under unroll)
    const float* __restrict__ tjfix,   // smem transT row (stride-65 base)
    unsigned char* __restrict__ histrow,
    float e_cur, int j)
{
    const float4* sp = (const float4*)sc_in;
    float gm[16];
#pragma unroll
    for (int g = 0; g < 16; g++) {
        float4 s4 = sp[g];
        float c0 = s4.x + tr[4 * g + 0];
        float c1 = s4.y + tr[4 * g + 1];
        float c2 = s4.z + tr[4 * g + 2];
        float c3 = s4.w + tr[4 * g + 3];
        gm[g] = fmaxf(fmaxf(c0, c1), fmaxf(c2, c3));
    }
    // keep-left (first-occurrence) merge tree over 16 groups
    float v1[8]; int b1[8];
#pragma unroll
    for (int k = 0; k < 8; k++) {
        bool p = gm[2 * k] >= gm[2 * k + 1];
        v1[k] = fmaxf(gm[2 * k], gm[2 * k + 1]);
        b1[k] = p ? 2 * k : 2 * k + 1;
    }
    float v2[4]; int b2[4];
#pragma unroll
    for (int k = 0; k < 4; k++) {
        bool p = v1[2 * k] >= v1[2 * k + 1];
        v2[k] = fmaxf(v1[2 * k], v1[2 * k + 1]);
        b2[k] = p ? b1[2 * k] : b1[2 * k + 1];
    }
    float v3[2]; int b3[2];
#pragma unroll
    for (int k = 0; k < 2; k++) {
        bool p = v2[2 * k] >= v2[2 * k + 1];
        v3[k] = fmaxf(v2[2 * k], v2[2 * k + 1]);
        b3[k] = p ? b2[2 * k] : b2[2 * k + 1];
    }
    bool pr = v3[0] >= v3[1];
    float best = fmaxf(v3[0], v3[1]);
    int gbase = (pr ? b3[0] : b3[1]) * 4;

    sc_out[j] = best + e_cur;          // EARLY STS: releases next step

    // index fixup in barrier shadow (bit-identical recompute -> exact ==)
    float f0 = sc_in[gbase + 0] + tjfix[gbase + 0];
    float f1 = sc_in[gbase + 1] + tjfix[gbase + 1];
    float f2 = sc_in[gbase + 2] + tjfix[gbase + 2];
    int idx = gbase + 3;
    if (f2 == best) idx = gbase + 2;
    if (f1 == best) idx = gbase + 1;
    if (f0 == best) idx = gbase + 0;
    histrow[j] = (unsigned char)idx;
}

__global__ __launch_bounds__(64) void viterbi_kernel(
    const float* __restrict__ emission,     // [B, T, N]
    const float* __restrict__ start_trans,  // [N]
    const float* __restrict__ end_trans,    // [N]
    const float* __restrict__ trans,        // [N, N] row-major
    float* __restrict__ tags_out,           // [B, T] as float
    int write_tags)
{
    extern __shared__ unsigned char dsm[];
    float* score  = (float*)dsm;                              // [2][NTAG]
    float* transT = (float*)(dsm + 2 * NTAG * 4);             // [NTAG][65]
    unsigned char* hist = dsm + 2 * NTAG * 4 + NTAG * 65 * 4; // [T][NTAG]

    const int b = blockIdx.x;
    const int j = threadIdx.x;   // 0..63

    float tr[64];
#pragma unroll
    for (int i = 0; i < 64; i++) {
        tr[i] = trans[i * NTAG + j];
        transT[j * 65 + i] = tr[i];
    }
    const float* tj = transT + j * 65;
    const float* eb = emission + (size_t)b * SEQ_T * NTAG;

    score[j] = start_trans[j] + eb[j];
    __syncthreads();

    // emission register pipeline: ep[k] = e[t0+k][j]
    float ep[4];
#pragma unroll
    for (int k = 0; k < 4; k++) ep[k] = eb[(size_t)(1 + k) * NTAG + j];

    int cur = 0;
    // main loop: t = 1,5,...,1017 (covers steps 1..1020)
    for (int t = 1; t <= SEQ_T - 7; t += 4) {
        float en[4];
#pragma unroll
        for (int k = 0; k < 4; k++) {
            int tt = t + 4 + k;
            if (tt > SEQ_T - 1) tt = SEQ_T - 1;
            en[k] = eb[(size_t)tt * NTAG + j];      // MLP=4, ~4 steps of cover
        }
#pragma unroll
        for (int u = 0; u < 4; u++) {
            vstep(score + cur * NTAG, score + (cur ^ 1) * NTAG,
                  tr, tj, hist + (size_t)(t + u) * NTAG, ep[u], j);
            __syncthreads();
            cur ^= 1;
        }
#pragma unroll
        for (int k = 0; k < 4; k++) ep[k] = en[k];
    }
    // remainder: steps 1021, 1022, 1023
#pragma unroll
    for (int u = 0; u < 3; u++) {
        vstep(score + cur * NTAG, score + (cur ^ 1) * NTAG,
              tr, tj, hist + (size_t)(SEQ_T - 3 + u) * NTAG, ep[u], j);
        __syncthreads();
        cur ^= 1;
    }

    score[cur * NTAG + j] += end_trans[j];
    __syncthreads();

    if (j == 0 && write_tags) {
        float bestv = score[cur * NTAG];
        int bt = 0;
        for (int jj = 1; jj < NTAG; jj++) {
            float v = score[cur * NTAG + jj];
            if (v > bestv) { bestv = v; bt = jj; }
        }
        float* to = tags_out + (size_t)b * SEQ_T;
        int tag = bt;
        to[SEQ_T - 1] = (float)tag;
        for (int t = SEQ_T - 1; t >= 1; t--) {
            tag = hist[(size_t)t * NTAG + tag];
            to[t - 1] = (float)tag;
        }
    }
}

// ---------------------------------------------------------------------------
// Host launcher
// ---------------------------------------------------------------------------
extern "C" void kernel_launch(void* const* d_in, const int* in_sizes, int n_in,
                              void* d_out, int out_size)
{
    const float* text        = (const float*)d_in[0];
    const float* W_em        = (const float*)d_in[2];
    const float* b_em        = (const float*)d_in[3];
    const float* start_trans = (const float*)d_in[4];
    const float* end_trans   = (const float*)d_in[5];
    const float* trans       = (const float*)d_in[6];
    float* out = (float*)d_out;

    emission_kernel<<<BT / TM, 128>>>(text, W_em, b_em, out);

    const int smem_bytes = 2 * NTAG * 4 + NTAG * 65 * 4 + SEQ_T * NTAG;
    cudaFuncSetAttribute(viterbi_kernel,
                         cudaFuncAttributeMaxDynamicSharedMemorySize, smem_bytes);
    const int write_tags = (out_size >= BTN + BT) ? 1 : 0;
    viterbi_kernel<<<BATCH, 64, smem_bytes>>>(
        out, start_trans, end_trans, trans, out + BTN, write_tags);
}